// round 13
// baseline (speedup 1.0000x reference)
#include <cuda_runtime.h>
#include <cuda_bf16.h>
#include <math.h>

// Problem constants
#define U_CNT 512
#define P_CNT 1024
#define D_DIM 128
#define H_DIM 256
#define E_CNT 98304
#define N_NODES 1536
#define CSR_CAP (E_CNT + N_NODES)

typedef unsigned long long u64;

// ---------------- packed f32x2 helpers (sm_100+) ------------------------------
__device__ __forceinline__ u64 pack2(float lo, float hi) {
    u64 r; asm("mov.b64 %0,{%1,%2};" : "=l"(r) : "f"(lo), "f"(hi)); return r;
}
__device__ __forceinline__ void unpack2(u64 v, float& lo, float& hi) {
    asm("mov.b64 {%0,%1},%2;" : "=f"(lo), "=f"(hi) : "l"(v));
}
__device__ __forceinline__ u64 add2(u64 a, u64 b) {
    u64 r; asm("add.rn.f32x2 %0,%1,%2;" : "=l"(r) : "l"(a), "l"(b)); return r;
}
__device__ __forceinline__ void fma2(u64& d, u64 a, u64 b) {
    asm("fma.rn.f32x2 %0,%1,%2,%0;" : "+l"(d) : "l"(a), "l"(b));
}
__device__ __forceinline__ u64 abs2(u64 a) {
    u64 r; asm("and.b64 %0,%1,0x7FFFFFFF7FFFFFFF;" : "=l"(r) : "l"(a)); return r;
}

// ---------------- scratch (device globals; no allocation allowed) -------------
__device__ float g_xA[N_NODES * H_DIM];
__device__ float g_xB[N_NODES * H_DIM];
__device__ float g_S0[N_NODES * H_DIM];   // agg partial, neighbor half 0
__device__ float g_S1[N_NODES * H_DIM];   // agg partial, neighbor half 1
__device__ int   g_deg[N_NODES];          // zero-init; scan resets each call
__device__ float g_dis[N_NODES];
__device__ int   g_ptr[N_NODES + 1];
__device__ int   g_cnt[N_NODES];          // zero-init; scan resets each call
__device__ int   g_src[CSR_CAP];
__device__ float g_C1[H_DIM * H_DIM];     // Wu @ Wq1[:128]
__device__ float g_C2[H_DIM * H_DIM];     // Wp @ Wq1[128:]
__device__ float g_bias1[H_DIM];          // bu @ Wq1[:128] + bq1
__device__ float g_bias2[H_DIM];          // bp @ Wq1[128:]
__device__ float g_AB[N_NODES * H_DIM];   // rows 0..511 = Au, 512..1535 = Bp

// ---------------- P1: x0 gather + degree count (round-2 exact) -----------------
__global__ void build_x0(const int* __restrict__ uid, const int* __restrict__ pid,
                         const float* __restrict__ ue, const float* __restrict__ pe,
                         const int* __restrict__ edge) {
    int i = blockIdx.x;           // node (1536)
    int d = threadIdx.x;          // feature (128)
    float v;
    if (i < U_CNT) v = ue[uid[i] * D_DIM + d];
    else           v = pe[pid[i - U_CNT] * D_DIM + d];
    g_xA[i * D_DIM + d] = v;
    int e = i * 128 + d;          // 196608 threads >= E
    if (e < E_CNT) atomicAdd(&g_deg[edge[E_CNT + e]], 1);
}

// ---------------- P2: single-warp scan (round-2 exact) --------------------------
__global__ void scan_kernel() {
    int lane = threadIdx.x;                 // 32 threads
    const int PER = N_NODES / 32;           // 48
    int base = lane * PER;
    int v[PER]; int s = 0;
    #pragma unroll
    for (int i = 0; i < PER; i++) v[i] = g_deg[base + i] + 1;
    #pragma unroll
    for (int i = 0; i < PER; i++) {
        g_dis[base + i] = rsqrtf((float)v[i]);
        s += v[i];
        g_deg[base + i] = 0;
        g_cnt[base + i] = 0;
    }
    int incl = s;
    #pragma unroll
    for (int off = 1; off < 32; off <<= 1) {
        int u = __shfl_up_sync(0xffffffffu, incl, off);
        if (lane >= off) incl += u;
    }
    int run = incl - s;                     // exclusive prefix
    if (lane == 0) g_ptr[0] = 0;
    #pragma unroll
    for (int i = 0; i < PER; i++) { run += v[i]; g_ptr[base + i + 1] = run; }
}

// ---------------- fp32 GEMM tile core (round-2 exact + optional X2 add) ---------
struct GemmS { float Xs[16][65]; float Ws[16][64]; };

__device__ __forceinline__ void gemm_core(
    GemmS& s, const float* __restrict__ X, const float* __restrict__ X2,
    const float* __restrict__ W,
    const float* __restrict__ bias, float* __restrict__ C,
    int N, int K, int bm, int bn, int relu)
{
    int tid = threadIdx.x;
    int tx = tid & 15, ty = tid >> 4;
    u64 acc[4][2] = {};
    for (int k0 = 0; k0 < K; k0 += 16) {
        {   // X tile: 64 rows x 16 k, transposed (X2 folded in if present)
            int kk = tid & 15, r = tid >> 4;
            #pragma unroll
            for (int rr = 0; rr < 4; rr++) {
                int idx = (bm + r + rr * 16) * K + k0 + kk;
                float v = X[idx];
                if (X2) v += X2[idx];
                s.Xs[kk][r + rr * 16] = v;
            }
        }
        {   // W tile: 16 k x 64 cols
            int c = tid & 63, kr = tid >> 6;
            #pragma unroll
            for (int rr = 0; rr < 4; rr++)
                s.Ws[kr + rr * 4][c] = W[(k0 + kr + rr * 4) * N + bn + c];
        }
        __syncthreads();
        #pragma unroll
        for (int k = 0; k < 16; k++) {
            float4 rb = *(const float4*)&s.Ws[k][tx * 4];
            u64 rb01 = pack2(rb.x, rb.y), rb23 = pack2(rb.z, rb.w);
            #pragma unroll
            for (int i = 0; i < 4; i++) {
                float a = s.Xs[k][ty * 4 + i];
                u64 a2 = pack2(a, a);
                fma2(acc[i][0], a2, rb01);
                fma2(acc[i][1], a2, rb23);
            }
        }
        __syncthreads();
    }
    #pragma unroll
    for (int i = 0; i < 4; i++) {
        int row = bm + ty * 4 + i;
        #pragma unroll
        for (int jp = 0; jp < 2; jp++) {
            float lo, hi; unpack2(acc[i][jp], lo, hi);
            int col = bn + tx * 4 + jp * 2;
            if (bias) { lo += bias[col]; hi += bias[col + 1]; }
            if (relu) { lo = fmaxf(lo, 0.f); hi = fmaxf(hi, 0.f); }
            float2 o = make_float2(lo, hi);
            *(float2*)&C[row * N + col] = o;
        }
    }
}

// ---------------- P3: CSR fill + projector weight products (piggyback) ---------
#define FILL_BLKS ((E_CNT + N_NODES + 255) / 256)        // 390
__global__ void fill_kernel(const int* __restrict__ edge,
                            const float* __restrict__ Wu, const float* __restrict__ bu,
                            const float* __restrict__ Wp, const float* __restrict__ bp,
                            const float* __restrict__ Wq1, const float* __restrict__ bq1) {
    __shared__ __align__(16) GemmS sm;
    int bx = blockIdx.x, tid = threadIdx.x;
    if (bx < FILL_BLKS) {
        int idx = bx * 256 + tid;
        if (idx >= E_CNT + N_NODES) return;
        int s, d;
        if (idx < E_CNT) { s = edge[idx]; d = edge[E_CNT + idx]; }
        else             { s = d = idx - E_CNT; }              // self loop
        int pos = g_ptr[d] + atomicAdd(&g_cnt[d], 1);
        g_src[pos] = s;
    } else if (bx < FILL_BLKS + 32) {
        int t = bx - FILL_BLKS;                 // 32 blocks: 16 per product
        int which = t >> 4, tt = t & 15;        // mt(4) x nt(4)
        int bm = (tt >> 2) * 64, bn = (tt & 3) * 64;
        if (which == 0)
            gemm_core(sm, Wu, nullptr, Wq1, nullptr, g_C1, H_DIM, D_DIM, bm, bn, 0);
        else
            gemm_core(sm, Wp, nullptr, Wq1 + D_DIM * H_DIM, nullptr, g_C2, H_DIM, D_DIM, bm, bn, 0);
    } else if (bx == FILL_BLKS + 32) {
        float acc = bq1[tid];
        for (int d = 0; d < D_DIM; d++) acc += bu[d] * Wq1[d * H_DIM + tid];
        g_bias1[tid] = acc;
    } else {
        float acc = 0.f;
        for (int d = 0; d < D_DIM; d++) acc += bp[d] * Wq1[(D_DIM + d) * H_DIM + tid];
        g_bias2[tid] = acc;
    }
}

// ---------------- aggregation: neighbor-split halves, round-2 inner loop --------
// grid (1536, 2): block (dst, half) sums its half of the neighbor list into
// S0/S1; the consuming GEMM adds the two planes in its X-tile load.
// partial[dst] = sum_{src in half(dst)} dis[src]*dis[dst] * h[src]

// F=128
__global__ void agg128_kernel(const float* __restrict__ h,
                              float* __restrict__ outA, float* __restrict__ outB) {
    __shared__ int   s_src[128];
    __shared__ float s_w[128];
    int dst = blockIdx.x, t = threadIdx.x;   // 128 threads
    int half = blockIdx.y;
    float dd = g_dis[dst];
    int s0 = g_ptr[dst], s1 = g_ptr[dst + 1];
    int mid = s0 + ((s1 - s0) >> 1);
    int lo = half ? mid : s0, hi = half ? s1 : mid;
    float ax = 0.f;
    for (int base = lo; base < hi; base += 128) {
        int n = min(128, hi - base);
        if (t < n) { int sc = g_src[base + t]; s_src[t] = sc; s_w[t] = g_dis[sc] * dd; }
        __syncthreads();
        #pragma unroll 4
        for (int i = 0; i < n; i++)
            ax += h[s_src[i] * 128 + t] * s_w[i];
        __syncthreads();
    }
    float* out = half ? outB : outA;
    out[dst * 128 + t] = ax;
}

// F=256 (round-2 float2 inner loop)
__global__ void agg256_kernel(const float* __restrict__ h,
                              float* __restrict__ outA, float* __restrict__ outB) {
    __shared__ int   s_src[128];
    __shared__ float s_w[128];
    int dst = blockIdx.x, t = threadIdx.x;   // 128 threads
    int half = blockIdx.y;
    float dd = g_dis[dst];
    int s0 = g_ptr[dst], s1 = g_ptr[dst + 1];
    int mid = s0 + ((s1 - s0) >> 1);
    int lo = half ? mid : s0, hi = half ? s1 : mid;
    float ax = 0.f, ay = 0.f;
    for (int base = lo; base < hi; base += 128) {
        int n = min(128, hi - base);
        if (t < n) { int sc = g_src[base + t]; s_src[t] = sc; s_w[t] = g_dis[sc] * dd; }
        __syncthreads();
        #pragma unroll 4
        for (int i = 0; i < n; i++) {
            float2 v = *(const float2*)(h + s_src[i] * 256 + 2 * t);
            ax += v.x * s_w[i]; ay += v.y * s_w[i];
        }
        __syncthreads();
    }
    float* out = half ? outB : outA;
    float2 o = make_float2(ax, ay);
    *(float2*)(out + dst * 256 + 2 * t) = o;
}

// ---------------- layer GEMM (64x64 tiles; X = X1 + X2) -------------------------
__global__ void gemm_kernel(const float* __restrict__ X, const float* __restrict__ X2,
                            const float* __restrict__ W,
                            const float* __restrict__ bias, float* __restrict__ C,
                            int N, int K, int relu) {
    __shared__ __align__(16) GemmS sm;
    gemm_core(sm, X, X2, W, bias, C, N, K, blockIdx.y * 64, blockIdx.x * 64, relu);
}

// fused projector: AB[r] = xA[r] @ (r<512 ? C1 : C2) + bias{1,2}
__global__ void gemm_ab_kernel(const float* __restrict__ X) {
    __shared__ __align__(16) GemmS sm;
    int bm = blockIdx.y * 64, bn = blockIdx.x * 64;
    if (bm < U_CNT)
        gemm_core(sm, X, nullptr, g_C1, g_bias1, g_AB, H_DIM, H_DIM, bm, bn, 0);
    else
        gemm_core(sm, X, nullptr, g_C2, g_bias2, g_AB, H_DIM, H_DIM, bm, bn, 0);
}

// ---------------- pairwise predictor (round-9 exact: 64x64 tiles) ---------------
// pred[u,p] = sigmoid(bq2 + sum_j relu(A[u,j]+B[p,j]) * w2[j])
// relu(s)*w = (w/2)*s + (w/2)*|s|
__global__ void pred_kernel(const float* __restrict__ w2, const float* __restrict__ bq2,
                            float* __restrict__ out) {
    __shared__ __align__(16) float As[64][34];
    __shared__ __align__(16) float Bs[64][34];
    __shared__ u64 wh2[16];
    const float* A = g_AB;                       // Au rows 0..511
    const float* B = g_AB + U_CNT * H_DIM;       // Bp rows 512..1535
    int tid = threadIdx.x;
    int tx = tid & 15, ty = tid >> 4;
    int u0 = blockIdx.y * 64, p0 = blockIdx.x * 64;
    u64 acc[4][4] = {};
    for (int j0 = 0; j0 < H_DIM; j0 += 32) {
        int c = tid & 31, r = tid >> 5;
        #pragma unroll
        for (int rr = 0; rr < 8; rr++) {
            As[r + rr * 8][c] = A[(u0 + r + rr * 8) * H_DIM + j0 + c];
            Bs[r + rr * 8][c] = B[(p0 + r + rr * 8) * H_DIM + j0 + c];
        }
        if (tid < 16) wh2[tid] = pack2(0.5f * w2[j0 + 2 * tid], 0.5f * w2[j0 + 2 * tid + 1]);
        __syncthreads();
        #pragma unroll
        for (int jp = 0; jp < 16; jp++) {
            u64 wv = wh2[jp];
            u64 av[4], bv[4];
            #pragma unroll
            for (int i = 0; i < 4; i++)  av[i] = *(const u64*)&As[ty + 16 * i][2 * jp];
            #pragma unroll
            for (int jj = 0; jj < 4; jj++) bv[jj] = *(const u64*)&Bs[tx + 16 * jj][2 * jp];
            #pragma unroll
            for (int i = 0; i < 4; i++)
                #pragma unroll
                for (int jj = 0; jj < 4; jj++) {
                    u64 s = add2(av[i], bv[jj]);
                    u64 a = abs2(s);
                    fma2(acc[i][jj], wv, s);
                    fma2(acc[i][jj], wv, a);
                }
        }
        __syncthreads();
    }
    float bb = bq2[0];
    #pragma unroll
    for (int i = 0; i < 4; i++) {
        int u = u0 + ty + 16 * i;
        #pragma unroll
        for (int jj = 0; jj < 4; jj++) {
            int p = p0 + tx + 16 * jj;
            float lo, hi; unpack2(acc[i][jj], lo, hi);
            float z = lo + hi + bb;
            out[u * P_CNT + p] = 1.f / (1.f + __expf(-z));
        }
    }
}

// ---------------- driver --------------------------------------------------------
extern "C" void kernel_launch(void* const* d_in, const int* in_sizes, int n_in,
                              void* d_out, int out_size) {
    const int*   uid  = (const int*)  d_in[0];
    const int*   pid  = (const int*)  d_in[1];
    const int*   edge = (const int*)  d_in[2];
    // d_in[3] = user_paper_interactions (unused by the reference math)
    const float* ue   = (const float*)d_in[4];
    const float* pe   = (const float*)d_in[5];
    const float* W0   = (const float*)d_in[6];  const float* b0 = (const float*)d_in[7];
    const float* W1   = (const float*)d_in[8];  const float* b1 = (const float*)d_in[9];
    const float* W2   = (const float*)d_in[10]; const float* b2 = (const float*)d_in[11];
    const float* Wu   = (const float*)d_in[12]; const float* bu = (const float*)d_in[13];
    const float* Wp   = (const float*)d_in[14]; const float* bp = (const float*)d_in[15];
    const float* Wq1  = (const float*)d_in[16]; const float* bq1= (const float*)d_in[17];
    const float* Wq2  = (const float*)d_in[18]; const float* bq2= (const float*)d_in[19];
    float* out = (float*)d_out;

    float *xA, *xB, *S0, *S1;
    cudaGetSymbolAddress((void**)&xA, g_xA);
    cudaGetSymbolAddress((void**)&xB, g_xB);
    cudaGetSymbolAddress((void**)&S0, g_S0);
    cudaGetSymbolAddress((void**)&S1, g_S1);

    // P1: x0 gather + degree count
    build_x0<<<N_NODES, D_DIM>>>(uid, pid, ue, pe, edge);
    // P2: degrees -> rsqrt + CSR row ptr
    scan_kernel<<<1, 32>>>();
    // P3: CSR fill + projector weight products (piggybacked)
    fill_kernel<<<FILL_BLKS + 34, 256>>>(edge, Wu, bu, Wp, bp, Wq1, bq1);

    // GCN layer 1 (aggregate-first, neighbor-split): xA[.,128] -> S0+S1 -> @W0
    agg128_kernel<<<dim3(N_NODES, 2), 128>>>(xA, S0, S1);
    gemm_kernel<<<dim3(H_DIM / 64, N_NODES / 64), 256>>>(S0, S1, W0, b0, xA, H_DIM, D_DIM, 1);
    // GCN layer 2
    agg256_kernel<<<dim3(N_NODES, 2), 128>>>(xA, S0, S1);
    gemm_kernel<<<dim3(H_DIM / 64, N_NODES / 64), 256>>>(S0, S1, W1, b1, xB, H_DIM, H_DIM, 1);
    // GCN layer 3
    agg256_kernel<<<dim3(N_NODES, 2), 128>>>(xB, S0, S1);
    gemm_kernel<<<dim3(H_DIM / 64, N_NODES / 64), 256>>>(S0, S1, W2, b2, xA, H_DIM, H_DIM, 1);

    // fused projector: AB = xA @ (C1|C2) + bias  (Au rows 0..511, Bp rows 512..1535)
    gemm_ab_kernel<<<dim3(H_DIM / 64, N_NODES / 64), 256>>>(xA);

    // pairwise sigmoid(relu(A[u]+B[p]) . w2 + bq2)
    pred_kernel<<<dim3(P_CNT / 64, U_CNT / 64), 256>>>(Wq2, bq2, out);
}

// round 15
// speedup vs baseline: 1.1148x; 1.1148x over previous
#include <cuda_runtime.h>
#include <cuda_bf16.h>
#include <math.h>

// Problem constants
#define U_CNT 512
#define P_CNT 1024
#define D_DIM 128
#define H_DIM 256
#define E_CNT 98304
#define N_NODES 1536
#define CSR_CAP (E_CNT + N_NODES)

typedef unsigned long long u64;

// ---------------- packed f32x2 helpers (sm_100+) ------------------------------
__device__ __forceinline__ u64 pack2(float lo, float hi) {
    u64 r; asm("mov.b64 %0,{%1,%2};" : "=l"(r) : "f"(lo), "f"(hi)); return r;
}
__device__ __forceinline__ void unpack2(u64 v, float& lo, float& hi) {
    asm("mov.b64 {%0,%1},%2;" : "=f"(lo), "=f"(hi) : "l"(v));
}
__device__ __forceinline__ u64 add2(u64 a, u64 b) {
    u64 r; asm("add.rn.f32x2 %0,%1,%2;" : "=l"(r) : "l"(a), "l"(b)); return r;
}
__device__ __forceinline__ void fma2(u64& d, u64 a, u64 b) {
    asm("fma.rn.f32x2 %0,%1,%2,%0;" : "+l"(d) : "l"(a), "l"(b));
}
__device__ __forceinline__ u64 abs2(u64 a) {
    u64 r; asm("and.b64 %0,%1,0x7FFFFFFF7FFFFFFF;" : "=l"(r) : "l"(a)); return r;
}

// ---------------- scratch (device globals; no allocation allowed) -------------
__device__ float g_xA[N_NODES * H_DIM];
__device__ float g_xB[N_NODES * H_DIM];
__device__ float g_h [N_NODES * H_DIM];
__device__ int   g_deg[N_NODES];          // zero-init; scan resets each call
__device__ float g_dis[N_NODES];
__device__ int   g_ptr[N_NODES + 1];
__device__ int   g_cnt[N_NODES];          // zero-init; scan resets each call
__device__ int   g_src[CSR_CAP];
__device__ int   g_flag;                  // scan-done flag; reset by build_x0
__device__ float g_C1[H_DIM * H_DIM];     // Wu @ Wq1[:128]
__device__ float g_C2[H_DIM * H_DIM];     // Wp @ Wq1[128:]
__device__ float g_bias1[H_DIM];          // bu @ Wq1[:128] + bq1
__device__ float g_bias2[H_DIM];          // bp @ Wq1[128:]
__device__ float g_AB[N_NODES * H_DIM];   // rows 0..511 = Au, 512..1535 = Bp

// ---------------- P1: x0 gather + degree count (round-2 exact + flag reset) ----
__global__ void build_x0(const int* __restrict__ uid, const int* __restrict__ pid,
                         const float* __restrict__ ue, const float* __restrict__ pe,
                         const int* __restrict__ edge) {
    int i = blockIdx.x;           // node (1536)
    int d = threadIdx.x;          // feature (128)
    if (i == 0 && d == 0) g_flag = 0;      // reset scan flag for this replay
    float v;
    if (i < U_CNT) v = ue[uid[i] * D_DIM + d];
    else           v = pe[pid[i - U_CNT] * D_DIM + d];
    g_xA[i * D_DIM + d] = v;
    int e = i * 128 + d;          // 196608 threads >= E
    if (e < E_CNT) atomicAdd(&g_deg[edge[E_CNT + e]], 1);
}

// ---------------- fp32 GEMM tile core (round-2 exact) ---------------------------
struct GemmS { float Xs[16][65]; float Ws[16][64]; };

__device__ __forceinline__ void gemm_core(
    GemmS& s, const float* __restrict__ X, const float* __restrict__ W,
    const float* __restrict__ bias, float* __restrict__ C,
    int N, int K, int bm, int bn, int relu)
{
    int tid = threadIdx.x;
    int tx = tid & 15, ty = tid >> 4;
    u64 acc[4][2] = {};
    for (int k0 = 0; k0 < K; k0 += 16) {
        {   // X tile: 64 rows x 16 k, transposed
            int kk = tid & 15, r = tid >> 4;
            #pragma unroll
            for (int rr = 0; rr < 4; rr++)
                s.Xs[kk][r + rr * 16] = X[(bm + r + rr * 16) * K + k0 + kk];
        }
        {   // W tile: 16 k x 64 cols
            int c = tid & 63, kr = tid >> 6;
            #pragma unroll
            for (int rr = 0; rr < 4; rr++)
                s.Ws[kr + rr * 4][c] = W[(k0 + kr + rr * 4) * N + bn + c];
        }
        __syncthreads();
        #pragma unroll
        for (int k = 0; k < 16; k++) {
            float4 rb = *(const float4*)&s.Ws[k][tx * 4];
            u64 rb01 = pack2(rb.x, rb.y), rb23 = pack2(rb.z, rb.w);
            #pragma unroll
            for (int i = 0; i < 4; i++) {
                float a = s.Xs[k][ty * 4 + i];
                u64 a2 = pack2(a, a);
                fma2(acc[i][0], a2, rb01);
                fma2(acc[i][1], a2, rb23);
            }
        }
        __syncthreads();
    }
    #pragma unroll
    for (int i = 0; i < 4; i++) {
        int row = bm + ty * 4 + i;
        #pragma unroll
        for (int jp = 0; jp < 2; jp++) {
            float lo, hi; unpack2(acc[i][jp], lo, hi);
            int col = bn + tx * 4 + jp * 2;
            if (bias) { lo += bias[col]; hi += bias[col + 1]; }
            if (relu) { lo = fmaxf(lo, 0.f); hi = fmaxf(hi, 0.f); }
            float2 o = make_float2(lo, hi);
            *(float2*)&C[row * N + col] = o;
        }
    }
}

// ---------------- P2: scan + CSR fill + projector products (one launch) --------
// blocks 0..389: edge/self-loop fill (prefetch edges, spin on scan flag)
// blocks 390..421: C1/C2 products   blocks 422,423: folded biases
// block  424: single-warp scan (deg+1, rsqrt, excl prefix -> ptr, reset, flag)
#define FILL_BLKS ((E_CNT + N_NODES + 255) / 256)        // 390
__global__ void fill_kernel(const int* __restrict__ edge,
                            const float* __restrict__ Wu, const float* __restrict__ bu,
                            const float* __restrict__ Wp, const float* __restrict__ bp,
                            const float* __restrict__ Wq1, const float* __restrict__ bq1) {
    __shared__ __align__(16) GemmS sm;
    int bx = blockIdx.x, tid = threadIdx.x;
    if (bx < FILL_BLKS) {
        int idx = bx * 256 + tid;
        bool live = idx < E_CNT + N_NODES;
        int s = 0, d = 0;
        if (live) {                         // prefetch before the spin
            if (idx < E_CNT) { s = edge[idx]; d = edge[E_CNT + idx]; }
            else             { s = d = idx - E_CNT; }          // self loop
        }
        if (tid == 0) {
            while (atomicAdd(&g_flag, 0) == 0) __nanosleep(64);
            __threadfence();
        }
        __syncthreads();
        if (live) {
            int pos = g_ptr[d] + atomicAdd(&g_cnt[d], 1);
            g_src[pos] = s;
        }
    } else if (bx < FILL_BLKS + 32) {
        int t = bx - FILL_BLKS;                 // 32 blocks: 16 per product
        int which = t >> 4, tt = t & 15;        // mt(4) x nt(4)
        int bm = (tt >> 2) * 64, bn = (tt & 3) * 64;
        if (which == 0)
            gemm_core(sm, Wu, Wq1, nullptr, g_C1, H_DIM, D_DIM, bm, bn, 0);
        else
            gemm_core(sm, Wp, Wq1 + D_DIM * H_DIM, nullptr, g_C2, H_DIM, D_DIM, bm, bn, 0);
    } else if (bx == FILL_BLKS + 32) {
        float acc = bq1[tid];
        for (int d = 0; d < D_DIM; d++) acc += bu[d] * Wq1[d * H_DIM + tid];
        g_bias1[tid] = acc;
    } else if (bx == FILL_BLKS + 33) {
        float acc = 0.f;
        for (int d = 0; d < D_DIM; d++) acc += bp[d] * Wq1[(D_DIM + d) * H_DIM + tid];
        g_bias2[tid] = acc;
    } else if (tid < 32) {
        // single-warp scan (round-2 exact body)
        int lane = tid;
        const int PER = N_NODES / 32;           // 48
        int base = lane * PER;
        int v[PER]; int ssum = 0;
        #pragma unroll
        for (int i = 0; i < PER; i++) v[i] = g_deg[base + i] + 1;
        #pragma unroll
        for (int i = 0; i < PER; i++) {
            g_dis[base + i] = rsqrtf((float)v[i]);
            ssum += v[i];
            g_deg[base + i] = 0;
            g_cnt[base + i] = 0;
        }
        int incl = ssum;
        #pragma unroll
        for (int off = 1; off < 32; off <<= 1) {
            int u = __shfl_up_sync(0xffffffffu, incl, off);
            if (lane >= off) incl += u;
        }
        int run = incl - ssum;                  // exclusive prefix
        if (lane == 0) g_ptr[0] = 0;
        #pragma unroll
        for (int i = 0; i < PER; i++) { run += v[i]; g_ptr[base + i + 1] = run; }
        __threadfence();                        // release
        __syncwarp();
        if (lane == 0) atomicExch(&g_flag, 1);
    }
}

// ---------------- aggregation (round-2 exact) ----------------------------------
// out[dst] = sum_{src in nb(dst)} dis[src]*dis[dst] * h[src]
template<int F>
__global__ void aggregate_kernel(const float* __restrict__ h, float* __restrict__ out) {
    __shared__ int   s_src[128];
    __shared__ float s_w[128];
    int dst = blockIdx.x, t = threadIdx.x;   // 128 threads
    float dd = g_dis[dst];
    int s0 = g_ptr[dst], s1 = g_ptr[dst + 1];
    float ax = 0.f, ay = 0.f;
    for (int base = s0; base < s1; base += 128) {
        int n = min(128, s1 - base);
        if (t < n) { int sc = g_src[base + t]; s_src[t] = sc; s_w[t] = g_dis[sc] * dd; }
        __syncthreads();
        if (F == 256) {
            #pragma unroll 4
            for (int i = 0; i < n; i++) {
                float2 v = *(const float2*)(h + s_src[i] * F + 2 * t);
                ax += v.x * s_w[i]; ay += v.y * s_w[i];
            }
        } else {
            #pragma unroll 4
            for (int i = 0; i < n; i++)
                ax += h[s_src[i] * F + t] * s_w[i];
        }
        __syncthreads();
    }
    if (F == 256) { float2 o = make_float2(ax, ay); *(float2*)(out + dst * F + 2 * t) = o; }
    else out[dst * F + t] = ax;
}

// ---------------- layer GEMM (64x64 tiles, round-2 exact) -----------------------
__global__ void gemm_kernel(const float* __restrict__ X, const float* __restrict__ W,
                            const float* __restrict__ bias, float* __restrict__ C,
                            int N, int K, int relu) {
    __shared__ __align__(16) GemmS sm;
    gemm_core(sm, X, W, bias, C, N, K, blockIdx.y * 64, blockIdx.x * 64, relu);
}

// fused projector: AB[r] = xA[r] @ (r<512 ? C1 : C2) + bias{1,2}
__global__ void gemm_ab_kernel(const float* __restrict__ X) {
    __shared__ __align__(16) GemmS sm;
    int bm = blockIdx.y * 64, bn = blockIdx.x * 64;
    if (bm < U_CNT)
        gemm_core(sm, X, g_C1, g_bias1, g_AB, H_DIM, H_DIM, bm, bn, 0);
    else
        gemm_core(sm, X, g_C2, g_bias2, g_AB, H_DIM, H_DIM, bm, bn, 0);
}

// ---------------- pairwise predictor: 64x64 tiles + linear-term factoring -------
// pred[u,p] = sigmoid(bq2 + sum_j relu(A[u,j]+B[p,j]) * w2[j])
// relu(s)*w = (w/2)*s + (w/2)*|s|
//   => z = 0.5<w,A_u> + 0.5<w,B_p> + sum_j (w/2)|A+B| + bq2
// linear terms accumulate per-row/col (8 fma2/step) instead of per-pair (16).
__global__ void pred_kernel(const float* __restrict__ w2, const float* __restrict__ bq2,
                            float* __restrict__ out) {
    __shared__ __align__(16) float As[64][34];
    __shared__ __align__(16) float Bs[64][34];
    __shared__ u64 wh2[16];
    const float* A = g_AB;                       // Au rows 0..511
    const float* B = g_AB + U_CNT * H_DIM;       // Bp rows 512..1535
    int tid = threadIdx.x;
    int tx = tid & 15, ty = tid >> 4;
    int u0 = blockIdx.y * 64, p0 = blockIdx.x * 64;
    u64 acc[4][4] = {};                          // |A+B| terms
    u64 cu[4] = {};                              // per-u linear terms
    u64 dp[4] = {};                              // per-p linear terms
    for (int j0 = 0; j0 < H_DIM; j0 += 32) {
        int c = tid & 31, r = tid >> 5;
        #pragma unroll
        for (int rr = 0; rr < 8; rr++) {
            As[r + rr * 8][c] = A[(u0 + r + rr * 8) * H_DIM + j0 + c];
            Bs[r + rr * 8][c] = B[(p0 + r + rr * 8) * H_DIM + j0 + c];
        }
        if (tid < 16) wh2[tid] = pack2(0.5f * w2[j0 + 2 * tid], 0.5f * w2[j0 + 2 * tid + 1]);
        __syncthreads();
        #pragma unroll
        for (int jp = 0; jp < 16; jp++) {
            u64 wv = wh2[jp];
            u64 av[4], bv[4];
            #pragma unroll
            for (int i = 0; i < 4; i++)  av[i] = *(const u64*)&As[ty + 16 * i][2 * jp];
            #pragma unroll
            for (int jj = 0; jj < 4; jj++) bv[jj] = *(const u64*)&Bs[tx + 16 * jj][2 * jp];
            #pragma unroll
            for (int i = 0; i < 4; i++)  fma2(cu[i], wv, av[i]);
            #pragma unroll
            for (int jj = 0; jj < 4; jj++) fma2(dp[jj], wv, bv[jj]);
            #pragma unroll
            for (int i = 0; i < 4; i++)
                #pragma unroll
                for (int jj = 0; jj < 4; jj++) {
                    u64 s = add2(av[i], bv[jj]);
                    u64 a = abs2(s);
                    fma2(acc[i][jj], wv, a);
                }
        }
        __syncthreads();
    }
    float bb = bq2[0];
    float cuf[4], dpf[4];
    #pragma unroll
    for (int i = 0; i < 4; i++) { float lo, hi; unpack2(cu[i], lo, hi); cuf[i] = lo + hi; }
    #pragma unroll
    for (int jj = 0; jj < 4; jj++) { float lo, hi; unpack2(dp[jj], lo, hi); dpf[jj] = lo + hi; }
    #pragma unroll
    for (int i = 0; i < 4; i++) {
        int u = u0 + ty + 16 * i;
        #pragma unroll
        for (int jj = 0; jj < 4; jj++) {
            int p = p0 + tx + 16 * jj;
            float lo, hi; unpack2(acc[i][jj], lo, hi);
            float z = lo + hi + cuf[i] + dpf[jj] + bb;
            out[u * P_CNT + p] = 1.f / (1.f + __expf(-z));
        }
    }
}

// ---------------- driver --------------------------------------------------------
extern "C" void kernel_launch(void* const* d_in, const int* in_sizes, int n_in,
                              void* d_out, int out_size) {
    const int*   uid  = (const int*)  d_in[0];
    const int*   pid  = (const int*)  d_in[1];
    const int*   edge = (const int*)  d_in[2];
    // d_in[3] = user_paper_interactions (unused by the reference math)
    const float* ue   = (const float*)d_in[4];
    const float* pe   = (const float*)d_in[5];
    const float* W0   = (const float*)d_in[6];  const float* b0 = (const float*)d_in[7];
    const float* W1   = (const float*)d_in[8];  const float* b1 = (const float*)d_in[9];
    const float* W2   = (const float*)d_in[10]; const float* b2 = (const float*)d_in[11];
    const float* Wu   = (const float*)d_in[12]; const float* bu = (const float*)d_in[13];
    const float* Wp   = (const float*)d_in[14]; const float* bp = (const float*)d_in[15];
    const float* Wq1  = (const float*)d_in[16]; const float* bq1= (const float*)d_in[17];
    const float* Wq2  = (const float*)d_in[18]; const float* bq2= (const float*)d_in[19];
    float* out = (float*)d_out;

    float *xA, *xB, *h;
    cudaGetSymbolAddress((void**)&xA, g_xA);
    cudaGetSymbolAddress((void**)&xB, g_xB);
    cudaGetSymbolAddress((void**)&h,  g_h);

    // P1: x0 gather + degree count (+ flag reset)
    build_x0<<<N_NODES, D_DIM>>>(uid, pid, ue, pe, edge);
    // P2: scan + CSR fill + projector weight products (one launch)
    fill_kernel<<<FILL_BLKS + 35, 256>>>(edge, Wu, bu, Wp, bp, Wq1, bq1);

    // GCN layer 1 (aggregate-first): xA[.,128] -> agg -> @W0 -> relu -> xA[.,256]
    aggregate_kernel<128><<<N_NODES, 128>>>(xA, xB);
    gemm_kernel<<<dim3(H_DIM / 64, N_NODES / 64), 256>>>(xB, W0, b0, xA, H_DIM, D_DIM, 1);
    // GCN layer 2
    aggregate_kernel<256><<<N_NODES, 128>>>(xA, h);
    gemm_kernel<<<dim3(H_DIM / 64, N_NODES / 64), 256>>>(h, W1, b1, xB, H_DIM, H_DIM, 1);
    // GCN layer 3
    aggregate_kernel<256><<<N_NODES, 128>>>(xB, h);
    gemm_kernel<<<dim3(H_DIM / 64, N_NODES / 64), 256>>>(h, W2, b2, xA, H_DIM, H_DIM, 1);

    // fused projector: AB = xA @ (C1|C2) + bias  (Au rows 0..511, Bp rows 512..1535)
    gemm_ab_kernel<<<dim3(H_DIM / 64, N_NODES / 64), 256>>>(xA);

    // pairwise sigmoid(relu(A[u]+B[p]) . w2 + bq2)
    pred_kernel<<<dim3(P_CNT / 64, U_CNT / 64), 256>>>(Wq2, bq2, out);
}